// round 4
// baseline (speedup 1.0000x reference)
#include <cuda_runtime.h>
#include <cuda_fp16.h>

// Problem constants
#define NC     5
#define NB     128000
#define BATCH  8
#define NJ     15
#define HH     128
#define WW     240
#define HMPIX  (HH*WW)        // 30720 pixels per (b,cam,j) heatmap

// Tiling: 1024 threads (32 warps). smem 123.8KB forces 1 CTA/SM; 32/64 warps.
#define THREADS 1024
#define BPT     25            // bins per thread (register accumulators)
#define GRP     5             // record prefetch group size (reg double-buffer)
#define NGRP    (BPT/GRP)     // 5 groups
#define CHUNK   (THREADS*BPT) // 25600 bins per CTA
#define NCHUNK  (NB/CHUNK)    // 5 chunks -> grid 5 x 15 x 8 = 600 CTAs

// Fused 8-byte per-(cam,bin) record (shared across all b,j):
//   .x = off (bits 0..15) | t_half_bits (bits 16..31)
//   .y = half2(vA, vB)
// Semantics: result = (vA,vB) . ( p0 + t*(p1-p0) )
// p0 = pair at off (row y0), p1 = pair at off+WW (smem row 128 is zero pad).
// All border (zeros-padding) cases are folded into (vA, vB, t) by prep.
__device__ uint2 g_rec[NC*NB];

__global__ void prep_kernel(const float* __restrict__ grid) {
    int idx = blockIdx.x * 256 + threadIdx.x;
    if (idx >= NC*NB) return;
    float2 g = reinterpret_cast<const float2*>(grid)[idx];

    // align_corners=True mapping
    float ix = (g.x + 1.0f) * 0.5f * (float)(WW - 1);
    float iy = (g.y + 1.0f) * 0.5f * (float)(HH - 1);
    float x0f = floorf(ix), y0f = floorf(iy);
    float fx = ix - x0f,    fy = iy - y0f;
    int   x0 = (int)x0f,    y0 = (int)y0f;

    // x: pair at xc provides (hm[y][xc], hm[y][xc+1]); fill zero-pads the
    // second element at xc==WW-1, so invalid x1 contributes 0.
    float wA, wB; int xc;
    if (x0 >= 0 && x0 < WW) { xc = x0; wA = 1.0f - fx; wB = fx;  }
    else if (x0 == -1)      { xc = 0;  wA = fx;        wB = 0.f; }
    else                    { xc = 0;  wA = 0.f;       wB = 0.f; }

    // y folded into (t, s): interior t=fy,s=1 (pad row zero handles y0=127);
    // y0==-1: use row 0 only, s=fy; fully OOB: s=0.
    float t, s; int yc;
    if (y0 >= 0 && y0 < HH) { yc = y0; t = fy;  s = 1.f; }
    else if (y0 == -1)      { yc = 0;  t = 0.f; s = fy;  }
    else                    { yc = 0;  t = 0.f; s = 0.f; }

    unsigned int off = (unsigned int)(yc * WW + xc);   // <= 30719, 15 bits
    __half th = __float2half_rn(t);
    __half2 v = __floats2half2_rn(wA * s, wB * s);

    uint2 r;
    r.x = off | ((unsigned int)__half_as_ushort(th) << 16);
    r.y = *reinterpret_cast<unsigned int*>(&v);
    g_rec[idx] = r;
}

__global__ __launch_bounds__(THREADS, 1)
void sample_kernel(const float* __restrict__ heatmaps,
                   float* __restrict__ out) {
    // Padded pair-heatmap: (HH+1) rows x WW pairs of fp16. 123,840 bytes.
    extern __shared__ __half2 sp[];

    const int tid   = threadIdx.x;
    const int chunk = blockIdx.x;
    const int j     = blockIdx.y;
    const int b     = blockIdx.z;
    const int base  = chunk * CHUNK;

    // Zero the pad row (row HH) once.
    if (tid < WW) sp[HMPIX + tid] = __floats2half2_rn(0.f, 0.f);

    // Vectorized fill x coord (first pixel of this thread's float4).
    // delta = (THREADS*4) % WW = 16.
    const int xstart = (tid * 4) % WW;

    float acc[BPT];
#pragma unroll
    for (int k = 0; k < BPT; ++k) acc[k] = 0.f;

    // Software pipeline: cur holds the records for the group about to be
    // computed; issued early so the L2 latency hides under fill/compute.
    uint2 cur[GRP];
#pragma unroll
    for (int u = 0; u < GRP; ++u)
        cur[u] = __ldg(g_rec + 0 * NB + base + u * THREADS + tid);

    for (int cam = 0; cam < NC; ++cam) {
        __syncthreads();  // previous gathers done (pad row visible, iter 0)

        // Build fp16 x-pair heatmap in smem (LDG.128 + shfl + STS.128).
        const float*  hm  = heatmaps + (((size_t)b * NC + cam) * NJ + j) * (size_t)HMPIX;
        const float4* hm4 = reinterpret_cast<const float4*>(hm);
        int x = xstart;
#pragma unroll
        for (int q = tid; q < HMPIX / 4; q += THREADS) {
            float4 v = __ldg(hm4 + q);
            float vn = __shfl_down_sync(0xffffffffu, v.x, 1);
            if ((tid & 31) == 31 && x != WW - 4)
                vn = __ldg(reinterpret_cast<const float*>(hm4 + q + 1));
            if (x == WW - 4) vn = 0.f;   // pair (239, OOB) -> zero

            __half2 h0 = __floats2half2_rn(v.x, v.y);
            __half2 h1 = __floats2half2_rn(v.y, v.z);
            __half2 h2 = __floats2half2_rn(v.z, v.w);
            __half2 h3 = __floats2half2_rn(v.w, vn);
            uint4 pk;
            pk.x = *reinterpret_cast<unsigned int*>(&h0);
            pk.y = *reinterpret_cast<unsigned int*>(&h1);
            pk.z = *reinterpret_cast<unsigned int*>(&h2);
            pk.w = *reinterpret_cast<unsigned int*>(&h3);
            *reinterpret_cast<uint4*>(sp + q * 4) = pk;

            x += 16;
            if (x >= WW) x -= WW;
        }
        __syncthreads();

        const uint2* __restrict__ rp = g_rec + cam * NB + base;

#pragma unroll
        for (int g = 0; g < NGRP; ++g) {
            // Prefetch next group's records (independent LDG.64 x GRP).
            uint2 nxt[GRP];
            if (g + 1 < NGRP) {
#pragma unroll
                for (int u = 0; u < GRP; ++u)
                    nxt[u] = __ldg(rp + ((g + 1) * GRP + u) * THREADS + tid);
            }
            // Compute current group from cur (records already in registers).
#pragma unroll
            for (int u = 0; u < GRP; ++u) {
                uint2 r = cur[u];
                unsigned int off = r.x & 0xFFFFu;
                __half2 t2  = __half2half2(__ushort_as_half((unsigned short)(r.x >> 16)));
                __half2 v01 = *reinterpret_cast<const __half2*>(&r.y);
                __half2 p0  = sp[off];        // (hm[y0][x0], hm[y0][x1])
                __half2 p1  = sp[off + WW];   // (hm[y1][x0], hm[y1][x1])
                __half2 pl  = __hfma2(__hsub2(p1, p0), t2, p0);   // row lerp
                __half2 pr  = __hmul2(pl, v01);                    // x weights
                float2 f    = __half22float2(pr);
                acc[g * GRP + u] += f.x + f.y;
            }
            if (g + 1 < NGRP) {
#pragma unroll
                for (int u = 0; u < GRP; ++u) cur[u] = nxt[u];
            }
        }

        // Preload next cam's first record group now — its L2 latency hides
        // under the next fill phase (barrier + 7.5 LDG.128/thread).
        if (cam + 1 < NC) {
            const uint2* __restrict__ rp2 = g_rec + (cam + 1) * NB + base;
#pragma unroll
            for (int u = 0; u < GRP; ++u)
                cur[u] = __ldg(rp2 + u * THREADS + tid);
        }
    }

    float* o = out + ((size_t)(b * NJ + j)) * NB + base;
#pragma unroll
    for (int k = 0; k < BPT; ++k) {
        float v = acc[k] * 0.2f;                          // mean over 5 cams
        o[k * THREADS + tid] = fminf(fmaxf(v, 0.f), 1.f); // clip [0,1]
    }
}

extern "C" void kernel_launch(void* const* d_in, const int* in_sizes, int n_in,
                              void* d_out, int out_size) {
    const float* heatmaps = (const float*)d_in[0];
    const float* grid     = (const float*)d_in[1];
    if (n_in >= 2 && in_sizes[0] == NC * NB * 2) {
        grid     = (const float*)d_in[0];
        heatmaps = (const float*)d_in[1];
    }

    const int smem_bytes = (HH + 1) * WW * (int)sizeof(__half2);  // 123,840 B
    cudaFuncSetAttribute(sample_kernel,
                         cudaFuncAttributeMaxDynamicSharedMemorySize, smem_bytes);

    prep_kernel<<<(NC * NB + 255) / 256, 256>>>(grid);

    dim3 g(NCHUNK, NJ, BATCH);
    sample_kernel<<<g, THREADS, smem_bytes>>>(heatmaps, (float*)d_out);
}